// round 8
// baseline (speedup 1.0000x reference)
#include <cuda_runtime.h>
#include <math.h>

// Problem constants
#define BB 256      // batch
#define RR 1152     // routes
#define CC 10       // caps
#define DD 16       // d_out
#define II 8        // d_in
#define NN 160      // CC*DD

// GEMM tiling
#define BT 64            // batch tile per block
#define RCHUNK 32        // routes per block (K split)
#define NKB 36           // RR / RCHUNK
#define NBT 4            // BB / BT
#define NSTAGE (RCHUNK/4)
#define GT 512           // gemm threads

#define BTB 8            // batch tile in t_kernel

typedef unsigned long long u64;

// Scratch (static device arrays; no allocation anywhere)
__device__ float g_wsumT[CC * II * RR];       // [c][i][r] sum_d W[r,c,d,i]
__device__ float g_t[CC * BB * RR];           // t[c][b][r] = sum_d u_hat
__device__ float g_spart[NKB * BB * NN];      // per-K-chunk partial s
__device__ float g_v[BB * NN];                // squashed v
__device__ float g_bT[NN * RR];               // routing logits, transposed [n][r]
__device__ float2 g_stats[NN];                // per-n {max, 1/sumexp}

// ---- packed f32x2 helpers (FFMA2 path on sm_103a) ----
__device__ __forceinline__ u64 pack2(float lo, float hi) {
    u64 r;
    asm("mov.b64 %0, {%1, %2};" : "=l"(r) : "f"(lo), "f"(hi));
    return r;
}
__device__ __forceinline__ float lo2(u64 v) { return __uint_as_float((unsigned int)v); }
__device__ __forceinline__ float hi2(u64 v) { return __uint_as_float((unsigned int)(v >> 32)); }
__device__ __forceinline__ void fma2(u64& d, u64 a, u64 b) {
    asm("fma.rn.f32x2 %0, %1, %2, %0;" : "+l"(d) : "l"(a), "l"(b));
}

// ---------------------------------------------------------------------------
// wsumT[c][i][r] = sum_d W[r,c,d,i]
// ---------------------------------------------------------------------------
__global__ void wsum_kernel(const float* __restrict__ W) {
    int id = blockIdx.x * blockDim.x + threadIdx.x;   // over RR*CC*II
    if (id >= RR * CC * II) return;
    int rc = id / II, i = id - rc * II;
    int r = rc / CC, c = rc - r * CC;
    const float* p = W + rc * DD * II + i;
    float s = 0.f;
    #pragma unroll
    for (int d = 0; d < DD; d++) s += p[d * II];
    g_wsumT[(c * II + i) * RR + r] = s;
}

// ---------------------------------------------------------------------------
// t[c][b][r] = sum_i wsumT[c][i][r] * u[b,r,i]   (iteration-invariant)
// ---------------------------------------------------------------------------
__global__ __launch_bounds__(128) void t_kernel(const float* __restrict__ u) {
    const int r = blockIdx.x * 128 + threadIdx.x;
    const int b0 = blockIdx.y * BTB;

    float uu[BTB][II];
    #pragma unroll
    for (int bi = 0; bi < BTB; bi++) {
        const float4* up = (const float4*)(u + ((b0 + bi) * RR + r) * II);
        float4 a = up[0], b = up[1];
        uu[bi][0] = a.x; uu[bi][1] = a.y; uu[bi][2] = a.z; uu[bi][3] = a.w;
        uu[bi][4] = b.x; uu[bi][5] = b.y; uu[bi][6] = b.z; uu[bi][7] = b.w;
    }

    #pragma unroll
    for (int c = 0; c < CC; c++) {
        float ws[II];
        #pragma unroll
        for (int i = 0; i < II; i++) ws[i] = g_wsumT[(c * II + i) * RR + r];
        #pragma unroll
        for (int bi = 0; bi < BTB; bi++) {
            float s = 0.f;
            #pragma unroll
            for (int i = 0; i < II; i++) s += ws[i] * uu[bi][i];
            g_t[(c * BB + b0 + bi) * RR + r] = s;
        }
    }
}

// ---------------------------------------------------------------------------
// s_part[kb][b][n] = sum_{r in chunk} softmax_c(r,n) * sum_i W[r,n,i]*u[b,r,i]
// c computed inline from bT + per-n stats. All smem traffic is 128-bit.
// 512 threads; thread (ty 0..15, tx 0..31): 4 b's x 5 n's, FFMA2 over i pairs.
// ---------------------------------------------------------------------------
__global__ __launch_bounds__(GT, 1) void gemm_kernel(
    const float* __restrict__ u, const float* __restrict__ W,
    int use_c, float cuni)
{
    __shared__ u64 u_s[4][BT][4];   // [rs][m][ip]  8 KB  (ip contiguous)
    __shared__ u64 w_s[4][NN][4];   // [rs][n][ip]  20 KB (ip contiguous)

    const int tid = threadIdx.x;
    const int tx = tid & 31, ty = tid >> 5;
    const int bt = blockIdx.x, kb = blockIdx.y;
    const int r0 = kb * RCHUNK;

    const u64 z = pack2(0.f, 0.f);
    u64 acc[4][5];
    #pragma unroll
    for (int jm = 0; jm < 4; jm++)
        #pragma unroll
        for (int jn = 0; jn < 5; jn++) acc[jm][jn] = z;

    // staging index decomposition (stage-invariant)
    const int sbl = tid & 63;          // b within tile
    const int srs = (tid >> 6) & 3;    // r within 4-row stage
    const int shalf = tid >> 8;        // i half
    int wrs[3], wn[3], wiq[3];
    bool wok[3];
    #pragma unroll
    for (int k = 0; k < 3; k++) {
        int idx = tid + GT * k;          // 0..1535, valid < 1280
        wok[k] = idx < 1280;
        int i2 = wok[k] ? idx : 0;
        wrs[k] = i2 / 320;
        int rem = i2 - wrs[k] * 320;
        wn[k] = rem >> 1;
        wiq[k] = rem & 1;
    }

    // prefetch registers
    float4 pu;
    float4 pw[3];
    float  pc[3];

    // coupling-coefficient generator (softmax inline)
    auto cval = [&](int r, int n) -> float {
        if (!use_c) return cuni;
        float2 st = g_stats[n];
        return expf(g_bT[n * RR + r] - st.x) * st.y;
    };

    // prologue: prefetch stage 0
    {
        pu = *(const float4*)(u + ((bt * BT + sbl) * RR + r0 + srs) * II + shalf * 4);
        #pragma unroll
        for (int k = 0; k < 3; k++) {
            if (wok[k]) {
                int r = r0 + wrs[k];
                pc[k] = cval(r, wn[k]);
                pw[k] = *(const float4*)(W + (r * NN + wn[k]) * II + wiq[k] * 4);
            }
        }
    }

    for (int st = 0; st < NSTAGE; st++) {
        if (st) __syncthreads();          // prev compute done reading smem

        // commit prefetched tile to smem (fold c into W) — 128-bit stores
        *(float4*)&u_s[srs][sbl][shalf * 2] = pu;
        #pragma unroll
        for (int k = 0; k < 3; k++) {
            if (wok[k]) {
                float4 wv = make_float4(pw[k].x * pc[k], pw[k].y * pc[k],
                                        pw[k].z * pc[k], pw[k].w * pc[k]);
                *(float4*)&w_s[wrs[k]][wn[k]][wiq[k] * 2] = wv;
            }
        }

        // prefetch next stage (overlaps with compute below)
        if (st < NSTAGE - 1) {
            const int rb = r0 + (st + 1) * 4;
            pu = *(const float4*)(u + ((bt * BT + sbl) * RR + rb + srs) * II + shalf * 4);
            #pragma unroll
            for (int k = 0; k < 3; k++) {
                if (wok[k]) {
                    int r = rb + wrs[k];
                    pc[k] = cval(r, wn[k]);
                    pw[k] = *(const float4*)(W + (r * NN + wn[k]) * II + wiq[k] * 4);
                }
            }
        }
        __syncthreads();

        #pragma unroll
        for (int rs = 0; rs < 4; rs++) {
            #pragma unroll
            for (int ipp = 0; ipp < 2; ipp++) {
                ulonglong2 uu[4], ww[5];
                #pragma unroll
                for (int jm = 0; jm < 4; jm++)
                    uu[jm] = *(const ulonglong2*)&u_s[rs][ty * 4 + jm][ipp * 2];
                #pragma unroll
                for (int jn = 0; jn < 5; jn++)
                    ww[jn] = *(const ulonglong2*)&w_s[rs][tx + 32 * jn][ipp * 2];
                #pragma unroll
                for (int jm = 0; jm < 4; jm++)
                    #pragma unroll
                    for (int jn = 0; jn < 5; jn++) {
                        fma2(acc[jm][jn], uu[jm].x, ww[jn].x);
                        fma2(acc[jm][jn], uu[jm].y, ww[jn].y);
                    }
            }
        }
    }

    #pragma unroll
    for (int jm = 0; jm < 4; jm++) {
        int b = bt * BT + ty * 4 + jm;
        #pragma unroll
        for (int jn = 0; jn < 5; jn++) {
            int n = tx + 32 * jn;
            g_spart[(kb * BB + b) * NN + n] = lo2(acc[jm][jn]) + hi2(acc[jm][jn]);
        }
    }
}

// ---------------------------------------------------------------------------
// Reduce K-chunk partials, squash, write v (and final output).
// grid 160 x 128 threads, float2 per thread; loads batched for MLP.
// ---------------------------------------------------------------------------
__global__ __launch_bounds__(128) void reduce_squash_kernel(float* __restrict__ dout) {
    const int idx2 = blockIdx.x * 128 + threadIdx.x;   // over BB*NN/2 = 20480
    const float2* sp = (const float2*)g_spart;
    const int stride2 = BB * NN / 2;

    float sx = 0.f, sy = 0.f;
    #pragma unroll
    for (int bat = 0; bat < 3; bat++) {
        float2 x[12];
        #pragma unroll
        for (int j = 0; j < 12; j++)
            x[j] = sp[(bat * 12 + j) * stride2 + idx2];
        float ax = 0.f, bx = 0.f, ay = 0.f, by = 0.f;
        #pragma unroll
        for (int j = 0; j < 12; j += 2) {
            ax += x[j].x;  ay += x[j].y;
            bx += x[j+1].x; by += x[j+1].y;
        }
        sx += ax + bx;
        sy += ay + by;
    }

    float2 o;
    {
        float sq = sx * sx;
        o.x = sq / (1.f + sq) * sx / (sqrtf(sq) + 1e-5f);
        sq = sy * sy;
        o.y = sq / (1.f + sq) * sy / (sqrtf(sq) + 1e-5f);
    }
    ((float2*)g_v)[idx2] = o;
    ((float2*)dout)[idx2] = o;
}

// ---------------------------------------------------------------------------
// bT[c*16+d][r] += (1/B) sum_b t[c][b][r] * v[b, c*16+d]
// ---------------------------------------------------------------------------
__global__ __launch_bounds__(128) void update_kernel(int first) {
    __shared__ u64 v_s[BB][DD / 2];   // 16 KB
    const int c = blockIdx.y;
    const int r = blockIdx.x * 128 + threadIdx.x;

    #pragma unroll
    for (int k = 0; k < 8; k++) {
        int idx = threadIdx.x + 128 * k;   // 0..1023
        int b = idx >> 2, q = idx & 3;
        const float4 v4 = *(const float4*)(g_v + b * NN + c * DD + q * 4);
        v_s[b][q * 2 + 0] = pack2(v4.x, v4.y);
        v_s[b][q * 2 + 1] = pack2(v4.z, v4.w);
    }
    __syncthreads();

    const u64 z = pack2(0.f, 0.f);
    u64 acc[8];
    #pragma unroll
    for (int j = 0; j < 8; j++) acc[j] = z;

    const float* tp = g_t + (c * BB) * RR + r;
    for (int b0 = 0; b0 < BB; b0 += 8) {
        float tv[8];
        #pragma unroll
        for (int q = 0; q < 8; q++) tv[q] = tp[(b0 + q) * RR];
        #pragma unroll
        for (int q = 0; q < 8; q++) {
            u64 t2 = pack2(tv[q], tv[q]);
            #pragma unroll
            for (int j = 0; j < 8; j++) fma2(acc[j], t2, v_s[b0 + q][j]);
        }
    }

    const float inv = 1.f / (float)BB;
    #pragma unroll
    for (int j = 0; j < 8; j++) {
        float x = lo2(acc[j]) * inv;
        float y = hi2(acc[j]) * inv;
        int o0 = (c * DD + 2 * j) * RR + r;
        int o1 = (c * DD + 2 * j + 1) * RR + r;
        if (!first) { x += g_bT[o0]; y += g_bT[o1]; }
        g_bT[o0] = x;
        g_bT[o1] = y;
    }
}

// ---------------------------------------------------------------------------
// stats[n] = {max_r bT[n][r], 1/sum_r exp(bT[n][r]-max)}.  grid NN, 128 thr.
// ---------------------------------------------------------------------------
__global__ __launch_bounds__(128) void stats_kernel() {
    __shared__ float red[128];
    const int n = blockIdx.x;
    const int tid = threadIdx.x;
    const float* bp = g_bT + n * RR;

    float vals[9];
    #pragma unroll
    for (int j = 0; j < 9; j++) vals[j] = bp[tid + 128 * j];

    float m = vals[0];
    #pragma unroll
    for (int j = 1; j < 9; j++) m = fmaxf(m, vals[j]);
    red[tid] = m;
    __syncthreads();
    for (int s = 64; s > 0; s >>= 1) {
        if (tid < s) red[tid] = fmaxf(red[tid], red[tid + s]);
        __syncthreads();
    }
    m = red[0];
    __syncthreads();

    float lsum = 0.f;
    #pragma unroll
    for (int j = 0; j < 9; j++) lsum += expf(vals[j] - m);
    red[tid] = lsum;
    __syncthreads();
    for (int s = 64; s > 0; s >>= 1) {
        if (tid < s) red[tid] += red[tid + s];
        __syncthreads();
    }
    if (tid == 0) g_stats[n] = make_float2(m, 1.f / red[0]);
}

// ---------------------------------------------------------------------------
extern "C" void kernel_launch(void* const* d_in, const int* in_sizes, int n_in,
                              void* d_out, int out_size) {
    const float* u = (const float*)d_in[0];   // (B, R, 8)
    const float* W = (const float*)d_in[1];   // (R, C, 16, 8)
    float* out = (float*)d_out;               // (B, C, 16) = 40960 floats

    wsum_kernel<<<(RR * CC * II + 255) / 256, 256>>>(W);
    t_kernel<<<dim3(RR / 128, BB / BTB), 128>>>(u);

    // Iteration 0: c_ij uniform = 1/R
    gemm_kernel<<<dim3(NBT, NKB), GT>>>(u, W, 0, 1.0f / (float)RR);
    reduce_squash_kernel<<<160, 128>>>(out);
    update_kernel<<<dim3(RR / 128, CC), 128>>>(1);
    stats_kernel<<<NN, 128>>>();

    // Iteration 1
    gemm_kernel<<<dim3(NBT, NKB), GT>>>(u, W, 1, 0.f);
    reduce_squash_kernel<<<160, 128>>>(out);
    update_kernel<<<dim3(RR / 128, CC), 128>>>(0);
    stats_kernel<<<NN, 128>>>();

    // Iteration 2 (final v -> out)
    gemm_kernel<<<dim3(NBT, NKB), GT>>>(u, W, 1, 0.f);
    reduce_squash_kernel<<<160, 128>>>(out);
}

// round 10
// speedup vs baseline: 1.2104x; 1.2104x over previous
#include <cuda_runtime.h>
#include <math.h>

// Problem constants
#define BB 256      // batch
#define RR 1152     // routes
#define CC 10       // caps
#define DD 16       // d_out
#define II 8        // d_in
#define NN 160      // CC*DD

// GEMM tiling
#define BT 64            // batch tile per block
#define RCHUNK 32        // routes per block (K split)
#define NKB 36           // RR / RCHUNK
#define NBT 4            // BB / BT
#define NSTAGE (RCHUNK/4)
#define GT 512           // gemm threads

#define BTB 8            // batch tile in t_kernel

typedef unsigned long long u64;

// Scratch (static device arrays; no allocation anywhere)
__device__ float g_wsumT[CC * II * RR];       // [c][i][r] sum_d W[r,c,d,i]
__device__ float g_t[CC * BB * RR];           // t[c][b][r] = sum_d u_hat
__device__ float g_spart[NKB * BB * NN];      // per-K-chunk partial s
__device__ float g_v[BB * NN];                // squashed v
__device__ float g_bT[NN * RR];               // routing logits, transposed [n][r]
__device__ float g_c[RR * NN];                // softmax(b) over r, [r][n]

// ---- packed f32x2 helpers (FFMA2 path on sm_103a) ----
__device__ __forceinline__ u64 pack2(float lo, float hi) {
    u64 r;
    asm("mov.b64 %0, {%1, %2};" : "=l"(r) : "f"(lo), "f"(hi));
    return r;
}
__device__ __forceinline__ float lo2(u64 v) { return __uint_as_float((unsigned int)v); }
__device__ __forceinline__ float hi2(u64 v) { return __uint_as_float((unsigned int)(v >> 32)); }
__device__ __forceinline__ void fma2(u64& d, u64 a, u64 b) {
    asm("fma.rn.f32x2 %0, %1, %2, %0;" : "+l"(d) : "l"(a), "l"(b));
}

// ---------------------------------------------------------------------------
// wsumT[c][i][r] = sum_d W[r,c,d,i]
// ---------------------------------------------------------------------------
__global__ void wsum_kernel(const float* __restrict__ W) {
    int id = blockIdx.x * blockDim.x + threadIdx.x;   // over RR*CC*II
    if (id >= RR * CC * II) return;
    int rc = id / II, i = id - rc * II;
    int r = rc / CC, c = rc - r * CC;
    const float* p = W + rc * DD * II + i;
    float s = 0.f;
    #pragma unroll
    for (int d = 0; d < DD; d++) s += p[d * II];
    g_wsumT[(c * II + i) * RR + r] = s;
}

// ---------------------------------------------------------------------------
// t[c][b][r] = sum_i wsumT[c][i][r] * u[b,r,i]   (iteration-invariant)
// ---------------------------------------------------------------------------
__global__ __launch_bounds__(128) void t_kernel(const float* __restrict__ u) {
    const int r = blockIdx.x * 128 + threadIdx.x;
    const int b0 = blockIdx.y * BTB;

    float uu[BTB][II];
    #pragma unroll
    for (int bi = 0; bi < BTB; bi++) {
        const float4* up = (const float4*)(u + ((b0 + bi) * RR + r) * II);
        float4 a = up[0], b = up[1];
        uu[bi][0] = a.x; uu[bi][1] = a.y; uu[bi][2] = a.z; uu[bi][3] = a.w;
        uu[bi][4] = b.x; uu[bi][5] = b.y; uu[bi][6] = b.z; uu[bi][7] = b.w;
    }

    #pragma unroll
    for (int c = 0; c < CC; c++) {
        float ws[II];
        #pragma unroll
        for (int i = 0; i < II; i++) ws[i] = g_wsumT[(c * II + i) * RR + r];
        #pragma unroll
        for (int bi = 0; bi < BTB; bi++) {
            float s = 0.f;
            #pragma unroll
            for (int i = 0; i < II; i++) s += ws[i] * uu[bi][i];
            g_t[(c * BB + b0 + bi) * RR + r] = s;
        }
    }
}

// ---------------------------------------------------------------------------
// s_part[kb][b][n] = sum_{r in chunk kb} c[r,n] * sum_i W[r,n,i]*u[b,r,i]
// Double-buffered smem: ONE __syncthreads per stage. Conflict-free layout
// w_s[rs][ip][n] (n contiguous). Coalesced staging incl. g_c reads.
// 512 threads; thread (ty 0..15, tx 0..31): 4 b's x 5 n's, FFMA2 over i pairs.
// ---------------------------------------------------------------------------
__global__ __launch_bounds__(GT, 1) void gemm_kernel(
    const float* __restrict__ u, const float* __restrict__ W,
    int use_c, float cuni)
{
    __shared__ u64 u_s[2][4][BT][4];   // [buf][rs][m][ip]  16 KB
    __shared__ u64 w_s[2][4][4][NN];   // [buf][rs][ip][n]  40 KB

    const int tid = threadIdx.x;
    const int tx = tid & 31, ty = tid >> 5;
    const int bt = blockIdx.x, kb = blockIdx.y;
    const int r0 = kb * RCHUNK;

    const u64 z = pack2(0.f, 0.f);
    u64 acc[4][5];
    #pragma unroll
    for (int jm = 0; jm < 4; jm++)
        #pragma unroll
        for (int jn = 0; jn < 5; jn++) acc[jm][jn] = z;

    // staging index decomposition (stage-invariant)
    const int sbl = tid & 63;          // b within tile
    const int srs = (tid >> 6) & 3;    // r within 4-row stage
    const int shalf = tid >> 8;        // i half
    int wrs[3], wn[3], wiq[3];
    bool wok[3];
    #pragma unroll
    for (int k = 0; k < 3; k++) {
        int idx = tid + GT * k;          // 0..1535, valid < 1280
        wok[k] = idx < 1280;
        int i2 = wok[k] ? idx : 0;
        wrs[k] = i2 / 320;
        int rem = i2 - wrs[k] * 320;
        wn[k] = rem >> 1;
        wiq[k] = rem & 1;
    }

    // prefetch registers
    float4 pu;
    float4 pw[3];
    float  pc[3];

    // prologue: prefetch stage 0
    {
        pu = *(const float4*)(u + ((bt * BT + sbl) * RR + r0 + srs) * II + shalf * 4);
        #pragma unroll
        for (int k = 0; k < 3; k++) {
            if (wok[k]) {
                int r = r0 + wrs[k];
                pc[k] = use_c ? g_c[r * NN + wn[k]] : cuni;
                pw[k] = *(const float4*)(W + (r * NN + wn[k]) * II + wiq[k] * 4);
            }
        }
    }

    #pragma unroll 2
    for (int st = 0; st < NSTAGE; st++) {
        const int buf = st & 1;

        // commit prefetched tile to smem (fold c into W)
        u_s[buf][srs][sbl][shalf * 2 + 0] = pack2(pu.x, pu.y);
        u_s[buf][srs][sbl][shalf * 2 + 1] = pack2(pu.z, pu.w);
        #pragma unroll
        for (int k = 0; k < 3; k++) {
            if (wok[k]) {
                w_s[buf][wrs[k]][wiq[k] * 2 + 0][wn[k]] = pack2(pw[k].x * pc[k], pw[k].y * pc[k]);
                w_s[buf][wrs[k]][wiq[k] * 2 + 1][wn[k]] = pack2(pw[k].z * pc[k], pw[k].w * pc[k]);
            }
        }
        __syncthreads();   // buf visible to all; also guards next commit to other buf

        // prefetch next stage (into registers; lands in the other buffer next iter)
        if (st < NSTAGE - 1) {
            const int rb = r0 + (st + 1) * 4;
            pu = *(const float4*)(u + ((bt * BT + sbl) * RR + rb + srs) * II + shalf * 4);
            #pragma unroll
            for (int k = 0; k < 3; k++) {
                if (wok[k]) {
                    int r = rb + wrs[k];
                    pc[k] = use_c ? g_c[r * NN + wn[k]] : cuni;
                    pw[k] = *(const float4*)(W + (r * NN + wn[k]) * II + wiq[k] * 4);
                }
            }
        }

        // compute on current buffer
        #pragma unroll
        for (int rs = 0; rs < 4; rs++) {
            #pragma unroll
            for (int ip = 0; ip < 4; ip++) {
                u64 uu[4], ww[5];
                #pragma unroll
                for (int jm = 0; jm < 4; jm++) uu[jm] = u_s[buf][rs][ty * 4 + jm][ip];
                #pragma unroll
                for (int jn = 0; jn < 5; jn++) ww[jn] = w_s[buf][rs][ip][tx + 32 * jn];
                #pragma unroll
                for (int jm = 0; jm < 4; jm++)
                    #pragma unroll
                    for (int jn = 0; jn < 5; jn++)
                        fma2(acc[jm][jn], uu[jm], ww[jn]);
            }
        }
    }

    #pragma unroll
    for (int jm = 0; jm < 4; jm++) {
        int b = bt * BT + ty * 4 + jm;
        #pragma unroll
        for (int jn = 0; jn < 5; jn++) {
            int n = tx + 32 * jn;
            g_spart[(kb * BB + b) * NN + n] = lo2(acc[jm][jn]) + hi2(acc[jm][jn]);
        }
    }
}

// ---------------------------------------------------------------------------
// Reduce K-chunk partials, squash, write v (and final output).
// grid 320 x 128 threads, scalar; loads batched 12-wide for MLP.
// ---------------------------------------------------------------------------
__global__ __launch_bounds__(128) void reduce_squash_kernel(float* __restrict__ dout) {
    const int idx = blockIdx.x * 128 + threadIdx.x;   // over BB*NN = 40960
    const int stride = BB * NN;

    float s = 0.f;
    #pragma unroll
    for (int bat = 0; bat < 3; bat++) {
        float x[12];
        #pragma unroll
        for (int j = 0; j < 12; j++)
            x[j] = g_spart[(bat * 12 + j) * stride + idx];
        float a0 = 0.f, a1 = 0.f, a2 = 0.f, a3 = 0.f;
        #pragma unroll
        for (int j = 0; j < 12; j += 4) {
            a0 += x[j]; a1 += x[j + 1]; a2 += x[j + 2]; a3 += x[j + 3];
        }
        s += (a0 + a1) + (a2 + a3);
    }

    float sq = s * s;
    float o = sq / (1.f + sq) * s / (sqrtf(sq) + 1e-5f);
    g_v[idx] = o;
    dout[idx] = o;
}

// ---------------------------------------------------------------------------
// bT[c*16+d][r] += (1/B) sum_b t[c][b][r] * v[b, c*16+d]
// ---------------------------------------------------------------------------
__global__ __launch_bounds__(128) void update_kernel(int first) {
    __shared__ u64 v_s[BB][DD / 2];   // 16 KB
    const int c = blockIdx.y;
    const int r = blockIdx.x * 128 + threadIdx.x;

    #pragma unroll
    for (int k = 0; k < 8; k++) {
        int idx = threadIdx.x + 128 * k;   // 0..1023
        int b = idx >> 2, q = idx & 3;
        const float4 v4 = *(const float4*)(g_v + b * NN + c * DD + q * 4);
        v_s[b][q * 2 + 0] = pack2(v4.x, v4.y);
        v_s[b][q * 2 + 1] = pack2(v4.z, v4.w);
    }
    __syncthreads();

    const u64 z = pack2(0.f, 0.f);
    u64 acc[8];
    #pragma unroll
    for (int j = 0; j < 8; j++) acc[j] = z;

    const float* tp = g_t + (c * BB) * RR + r;
    for (int b0 = 0; b0 < BB; b0 += 8) {
        float tv[8];
        #pragma unroll
        for (int q = 0; q < 8; q++) tv[q] = tp[(b0 + q) * RR];
        #pragma unroll
        for (int q = 0; q < 8; q++) {
            u64 t2 = pack2(tv[q], tv[q]);
            #pragma unroll
            for (int j = 0; j < 8; j++) fma2(acc[j], t2, v_s[b0 + q][j]);
        }
    }

    const float inv = 1.f / (float)BB;
    #pragma unroll
    for (int j = 0; j < 8; j++) {
        float x = lo2(acc[j]) * inv;
        float y = hi2(acc[j]) * inv;
        int o0 = (c * DD + 2 * j) * RR + r;
        int o1 = (c * DD + 2 * j + 1) * RR + r;
        if (!first) { x += g_bT[o0]; y += g_bT[o1]; }
        g_bT[o0] = x;
        g_bT[o1] = y;
    }
}

// ---------------------------------------------------------------------------
// c[r,n] = softmax over r of bT[n][r].  grid NN blocks, 128 threads.
// Coalesced reads from bT; scattered (cheap) stores into g_c[r][n].
// ---------------------------------------------------------------------------
__global__ __launch_bounds__(128) void softmax_kernel() {
    __shared__ float red[128];
    const int n = blockIdx.x;
    const int tid = threadIdx.x;
    const float* bp = g_bT + n * RR;

    float vals[9];
    #pragma unroll
    for (int j = 0; j < 9; j++) vals[j] = bp[tid + 128 * j];

    float m = vals[0];
    #pragma unroll
    for (int j = 1; j < 9; j++) m = fmaxf(m, vals[j]);
    red[tid] = m;
    __syncthreads();
    for (int s = 64; s > 0; s >>= 1) {
        if (tid < s) red[tid] = fmaxf(red[tid], red[tid + s]);
        __syncthreads();
    }
    m = red[0];
    __syncthreads();

    float e[9];
    float lsum = 0.f;
    #pragma unroll
    for (int j = 0; j < 9; j++) { e[j] = expf(vals[j] - m); lsum += e[j]; }
    red[tid] = lsum;
    __syncthreads();
    for (int s = 64; s > 0; s >>= 1) {
        if (tid < s) red[tid] += red[tid + s];
        __syncthreads();
    }
    float inv = 1.f / red[0];

    #pragma unroll
    for (int j = 0; j < 9; j++)
        g_c[(tid + 128 * j) * NN + n] = e[j] * inv;
}

// ---------------------------------------------------------------------------
extern "C" void kernel_launch(void* const* d_in, const int* in_sizes, int n_in,
                              void* d_out, int out_size) {
    const float* u = (const float*)d_in[0];   // (B, R, 8)
    const float* W = (const float*)d_in[1];   // (R, C, 16, 8)
    float* out = (float*)d_out;               // (B, C, 16) = 40960 floats

    wsum_kernel<<<(RR * CC * II + 255) / 256, 256>>>(W);
    t_kernel<<<dim3(RR / 128, BB / BTB), 128>>>(u);

    // Iteration 0: c_ij uniform = 1/R
    gemm_kernel<<<dim3(NBT, NKB), GT>>>(u, W, 0, 1.0f / (float)RR);
    reduce_squash_kernel<<<320, 128>>>(out);
    update_kernel<<<dim3(RR / 128, CC), 128>>>(1);
    softmax_kernel<<<NN, 128>>>();

    // Iteration 1
    gemm_kernel<<<dim3(NBT, NKB), GT>>>(u, W, 1, 0.f);
    reduce_squash_kernel<<<320, 128>>>(out);
    update_kernel<<<dim3(RR / 128, CC), 128>>>(0);
    softmax_kernel<<<NN, 128>>>();

    // Iteration 2 (final v -> out)
    gemm_kernel<<<dim3(NBT, NKB), GT>>>(u, W, 1, 0.f);
    reduce_squash_kernel<<<320, 128>>>(out);
}

// round 11
// speedup vs baseline: 1.3291x; 1.0980x over previous
#include <cuda_runtime.h>
#include <math.h>

// Problem constants
#define BB 256      // batch
#define RR 1152     // routes
#define CC 10       // caps
#define DD 16       // d_out
#define II 8        // d_in
#define NN 160      // CC*DD

// GEMM tiling
#define BT 64            // batch tile per block
#define RCHUNK 32        // routes per block (K split)
#define NKB 36           // RR / RCHUNK
#define NBT 4            // BB / BT
#define NSTAGE (RCHUNK/4)
#define GT 256           // gemm threads

#define BTB 8            // batch tile in t_kernel

typedef unsigned long long u64;

// Scratch (static device arrays; no allocation anywhere)
__device__ float g_wsumT[CC * II * RR];       // [c][i][r] sum_d W[r,c,d,i]
__device__ float g_t[CC * BB * RR];           // t[c][b][r] = sum_d u_hat
__device__ float g_spart[NKB * BB * NN];      // per-K-chunk partial s
__device__ float g_v[BB * NN];                // squashed v
__device__ float g_bT[NN * RR];               // routing logits, transposed [n][r]
__device__ float g_c[RR * NN];                // softmax(b) over r, [r][n]

// ---- packed f32x2 helpers (FFMA2 path on sm_103a) ----
__device__ __forceinline__ u64 pack2(float lo, float hi) {
    u64 r;
    asm("mov.b64 %0, {%1, %2};" : "=l"(r) : "f"(lo), "f"(hi));
    return r;
}
__device__ __forceinline__ float lo2(u64 v) { return __uint_as_float((unsigned int)v); }
__device__ __forceinline__ float hi2(u64 v) { return __uint_as_float((unsigned int)(v >> 32)); }
__device__ __forceinline__ void fma2(u64& d, u64 a, u64 b) {
    asm("fma.rn.f32x2 %0, %1, %2, %0;" : "+l"(d) : "l"(a), "l"(b));
}

// ---------------------------------------------------------------------------
// wsumT[c][i][r] = sum_d W[r,c,d,i]
// ---------------------------------------------------------------------------
__global__ void wsum_kernel(const float* __restrict__ W) {
    int id = blockIdx.x * blockDim.x + threadIdx.x;   // over RR*CC*II
    if (id >= RR * CC * II) return;
    int rc = id / II, i = id - rc * II;
    int r = rc / CC, c = rc - r * CC;
    const float* p = W + rc * DD * II + i;
    float s = 0.f;
    #pragma unroll
    for (int d = 0; d < DD; d++) s += p[d * II];
    g_wsumT[(c * II + i) * RR + r] = s;
}

// ---------------------------------------------------------------------------
// t[c][b][r] = sum_i wsumT[c][i][r] * u[b,r,i]   (iteration-invariant)
// ---------------------------------------------------------------------------
__global__ __launch_bounds__(128) void t_kernel(const float* __restrict__ u) {
    const int r = blockIdx.x * 128 + threadIdx.x;
    const int b0 = blockIdx.y * BTB;

    float uu[BTB][II];
    #pragma unroll
    for (int bi = 0; bi < BTB; bi++) {
        const float4* up = (const float4*)(u + ((b0 + bi) * RR + r) * II);
        float4 a = up[0], b = up[1];
        uu[bi][0] = a.x; uu[bi][1] = a.y; uu[bi][2] = a.z; uu[bi][3] = a.w;
        uu[bi][4] = b.x; uu[bi][5] = b.y; uu[bi][6] = b.z; uu[bi][7] = b.w;
    }

    #pragma unroll
    for (int c = 0; c < CC; c++) {
        float ws[II];
        #pragma unroll
        for (int i = 0; i < II; i++) ws[i] = g_wsumT[(c * II + i) * RR + r];
        #pragma unroll
        for (int bi = 0; bi < BTB; bi++) {
            float s = 0.f;
            #pragma unroll
            for (int i = 0; i < II; i++) s += ws[i] * uu[bi][i];
            g_t[(c * BB + b0 + bi) * RR + r] = s;
        }
    }
}

// ---------------------------------------------------------------------------
// s_part[kb][b][n] = sum_{r in chunk kb} c[r,n] * sum_i W[r,n,i]*u[b,r,i]
// 256 threads; thread (ty 0..7, tx 0..31): 8 b's x 5 n's (register blocked
// to halve W smem traffic per FMA -> fma-pipe bound, not crossbar bound).
// Double-buffered smem, ONE __syncthreads per stage.
// ---------------------------------------------------------------------------
__global__ __launch_bounds__(GT, 1) void gemm_kernel(
    const float* __restrict__ u, const float* __restrict__ W,
    int use_c, float cuni)
{
    __shared__ u64 u_s[2][4][BT][4];   // [buf][rs][m][ip]  16 KB
    __shared__ u64 w_s[2][4][4][NN];   // [buf][rs][ip][n]  40 KB

    const int tid = threadIdx.x;
    const int tx = tid & 31, ty = tid >> 5;   // ty 0..7
    const int bt = blockIdx.x, kb = blockIdx.y;
    const int r0 = kb * RCHUNK;

    const u64 z = pack2(0.f, 0.f);
    u64 acc[8][5];
    #pragma unroll
    for (int jm = 0; jm < 8; jm++)
        #pragma unroll
        for (int jn = 0; jn < 5; jn++) acc[jm][jn] = z;

    // ---- staging decomposition (stage-invariant) ----
    // u tile: 512 float4 entries; thread handles idx = tid (half 0) and tid+256 (half 1)
    const int sbl = tid & 63;          // b within tile
    const int srs = (tid >> 6) & 3;    // r within 4-row stage
    // running offset for u loads (element units)
    const float* ubase = u + ((bt * BT + sbl) * RR + r0 + srs) * II;

    // W tile: 1280 float4 entries; thread handles idx = tid + 256k, k<5 (exact)
    int wo[5];      // running offset o = r*NN + n (element/4 units in W, exact in g_c)
    int wiq[5], wrs[5], wn[5];
    #pragma unroll
    for (int k = 0; k < 5; k++) {
        int idx = tid + GT * k;          // 0..1279
        wrs[k] = idx / 320;
        int rem = idx - wrs[k] * 320;
        wn[k] = rem >> 1;
        wiq[k] = rem & 1;
        wo[k] = (r0 + wrs[k]) * NN + wn[k];
    }

    // prefetch registers
    float4 pu0, pu1;
    float4 pw[5];
    float  pc[5];

    // prologue: prefetch stage 0
    {
        pu0 = *(const float4*)(ubase);
        pu1 = *(const float4*)(ubase + 4);
        #pragma unroll
        for (int k = 0; k < 5; k++) {
            pc[k] = use_c ? g_c[wo[k]] : cuni;
            pw[k] = *(const float4*)(W + wo[k] * 8 + wiq[k] * 4);
        }
    }

    #pragma unroll 2
    for (int st = 0; st < NSTAGE; st++) {
        const int buf = st & 1;

        // commit prefetched tile to smem (fold c into W)
        *(float4*)&u_s[buf][srs][sbl][0] = pu0;
        *(float4*)&u_s[buf][srs][sbl][2] = pu1;
        #pragma unroll
        for (int k = 0; k < 5; k++) {
            w_s[buf][wrs[k]][wiq[k] * 2 + 0][wn[k]] = pack2(pw[k].x * pc[k], pw[k].y * pc[k]);
            w_s[buf][wrs[k]][wiq[k] * 2 + 1][wn[k]] = pack2(pw[k].z * pc[k], pw[k].w * pc[k]);
        }
        __syncthreads();   // buf visible; also guards next commit to other buf

        // prefetch next stage (lands in the other buffer next iter)
        if (st < NSTAGE - 1) {
            const float* ub = ubase + (st + 1) * (4 * II);
            pu0 = *(const float4*)(ub);
            pu1 = *(const float4*)(ub + 4);
            #pragma unroll
            for (int k = 0; k < 5; k++) {
                int o = wo[k] + (st + 1) * (4 * NN);
                pc[k] = use_c ? g_c[o] : cuni;
                pw[k] = *(const float4*)(W + o * 8 + wiq[k] * 4);
            }
        }

        // compute on current buffer: 8b x 5n per thread
        #pragma unroll
        for (int rs = 0; rs < 4; rs++) {
            #pragma unroll
            for (int ip = 0; ip < 4; ip++) {
                u64 ww[5];
                #pragma unroll
                for (int jn = 0; jn < 5; jn++) ww[jn] = w_s[buf][rs][ip][tx + 32 * jn];
                #pragma unroll
                for (int jm = 0; jm < 8; jm++) {
                    u64 uv = u_s[buf][rs][ty * 8 + jm][ip];   // broadcast
                    #pragma unroll
                    for (int jn = 0; jn < 5; jn++)
                        fma2(acc[jm][jn], uv, ww[jn]);
                }
            }
        }
    }

    #pragma unroll
    for (int jm = 0; jm < 8; jm++) {
        int b = bt * BT + ty * 8 + jm;
        #pragma unroll
        for (int jn = 0; jn < 5; jn++) {
            int n = tx + 32 * jn;
            g_spart[(kb * BB + b) * NN + n] = lo2(acc[jm][jn]) + hi2(acc[jm][jn]);
        }
    }
}

// ---------------------------------------------------------------------------
// Reduce K-chunk partials, squash, write v (and final output).
// grid 320 x 128 threads, scalar; loads batched 12-wide for MLP.
// ---------------------------------------------------------------------------
__global__ __launch_bounds__(128) void reduce_squash_kernel(float* __restrict__ dout) {
    const int idx = blockIdx.x * 128 + threadIdx.x;   // over BB*NN = 40960
    const int stride = BB * NN;

    float s = 0.f;
    #pragma unroll
    for (int bat = 0; bat < 3; bat++) {
        float x[12];
        #pragma unroll
        for (int j = 0; j < 12; j++)
            x[j] = g_spart[(bat * 12 + j) * stride + idx];
        float a0 = 0.f, a1 = 0.f, a2 = 0.f, a3 = 0.f;
        #pragma unroll
        for (int j = 0; j < 12; j += 4) {
            a0 += x[j]; a1 += x[j + 1]; a2 += x[j + 2]; a3 += x[j + 3];
        }
        s += (a0 + a1) + (a2 + a3);
    }

    float sq = s * s;
    float o = sq / (1.f + sq) * s / (sqrtf(sq) + 1e-5f);
    g_v[idx] = o;
    dout[idx] = o;
}

// ---------------------------------------------------------------------------
// bT[c*16+d][r] += (1/B) sum_b t[c][b][r] * v[b, c*16+d]
// ---------------------------------------------------------------------------
__global__ __launch_bounds__(128) void update_kernel(int first) {
    __shared__ u64 v_s[BB][DD / 2];   // 16 KB
    const int c = blockIdx.y;
    const int r = blockIdx.x * 128 + threadIdx.x;

    #pragma unroll
    for (int k = 0; k < 8; k++) {
        int idx = threadIdx.x + 128 * k;   // 0..1023
        int b = idx >> 2, q = idx & 3;
        const float4 v4 = *(const float4*)(g_v + b * NN + c * DD + q * 4);
        v_s[b][q * 2 + 0] = pack2(v4.x, v4.y);
        v_s[b][q * 2 + 1] = pack2(v4.z, v4.w);
    }
    __syncthreads();

    const u64 z = pack2(0.f, 0.f);
    u64 acc[8];
    #pragma unroll
    for (int j = 0; j < 8; j++) acc[j] = z;

    const float* tp = g_t + (c * BB) * RR + r;
    for (int b0 = 0; b0 < BB; b0 += 8) {
        float tv[8];
        #pragma unroll
        for (int q = 0; q < 8; q++) tv[q] = tp[(b0 + q) * RR];
        #pragma unroll
        for (int q = 0; q < 8; q++) {
            u64 t2 = pack2(tv[q], tv[q]);
            #pragma unroll
            for (int j = 0; j < 8; j++) fma2(acc[j], t2, v_s[b0 + q][j]);
        }
    }

    const float inv = 1.f / (float)BB;
    #pragma unroll
    for (int j = 0; j < 8; j++) {
        float x = lo2(acc[j]) * inv;
        float y = hi2(acc[j]) * inv;
        int o0 = (c * DD + 2 * j) * RR + r;
        int o1 = (c * DD + 2 * j + 1) * RR + r;
        if (!first) { x += g_bT[o0]; y += g_bT[o1]; }
        g_bT[o0] = x;
        g_bT[o1] = y;
    }
}

// ---------------------------------------------------------------------------
// c[r,n] = softmax over r of bT[n][r].  grid NN blocks, 128 threads.
// ---------------------------------------------------------------------------
__global__ __launch_bounds__(128) void softmax_kernel() {
    __shared__ float red[128];
    const int n = blockIdx.x;
    const int tid = threadIdx.x;
    const float* bp = g_bT + n * RR;

    float vals[9];
    #pragma unroll
    for (int j = 0; j < 9; j++) vals[j] = bp[tid + 128 * j];

    float m = vals[0];
    #pragma unroll
    for (int j = 1; j < 9; j++) m = fmaxf(m, vals[j]);
    red[tid] = m;
    __syncthreads();
    for (int s = 64; s > 0; s >>= 1) {
        if (tid < s) red[tid] = fmaxf(red[tid], red[tid + s]);
        __syncthreads();
    }
    m = red[0];
    __syncthreads();

    float e[9];
    float lsum = 0.f;
    #pragma unroll
    for (int j = 0; j < 9; j++) { e[j] = expf(vals[j] - m); lsum += e[j]; }
    red[tid] = lsum;
    __syncthreads();
    for (int s = 64; s > 0; s >>= 1) {
        if (tid < s) red[tid] += red[tid + s];
        __syncthreads();
    }
    float inv = 1.f / red[0];

    #pragma unroll
    for (int j = 0; j < 9; j++)
        g_c[(tid + 128 * j) * NN + n] = e[j] * inv;
}

// ---------------------------------------------------------------------------
extern "C" void kernel_launch(void* const* d_in, const int* in_sizes, int n_in,
                              void* d_out, int out_size) {
    const float* u = (const float*)d_in[0];   // (B, R, 8)
    const float* W = (const float*)d_in[1];   // (R, C, 16, 8)
    float* out = (float*)d_out;               // (B, C, 16) = 40960 floats

    wsum_kernel<<<(RR * CC * II + 255) / 256, 256>>>(W);
    t_kernel<<<dim3(RR / 128, BB / BTB), 128>>>(u);

    // Iteration 0: c_ij uniform = 1/R
    gemm_kernel<<<dim3(NBT, NKB), GT>>>(u, W, 0, 1.0f / (float)RR);
    reduce_squash_kernel<<<320, 128>>>(out);
    update_kernel<<<dim3(RR / 128, CC), 128>>>(1);
    softmax_kernel<<<NN, 128>>>();

    // Iteration 1
    gemm_kernel<<<dim3(NBT, NKB), GT>>>(u, W, 1, 0.f);
    reduce_squash_kernel<<<320, 128>>>(out);
    update_kernel<<<dim3(RR / 128, CC), 128>>>(0);
    softmax_kernel<<<NN, 128>>>();

    // Iteration 2 (final v -> out)
    gemm_kernel<<<dim3(NBT, NKB), GT>>>(u, W, 1, 0.f);
    reduce_squash_kernel<<<320, 128>>>(out);
}